// round 6
// baseline (speedup 1.0000x reference)
#include <cuda_runtime.h>
#include <cstdint>

#define N_NODES 100000
#define N_EDGES 600000
#define IN_C    128
#define OUT_C   128
#define M_TILE  128
#define N_TILES ((N_NODES + M_TILE - 1) / M_TILE)   // 782
#define M_PAD   (N_TILES * M_TILE)                  // 100096
#define KCH     32                                  // K per staged chunk
#define NCHUNK  (IN_C / KCH)                        // 4

// Fragment-ready smem buffers: A_frag / B_frag, 4096 floats (16 KB) each,
// double-buffered -> 64 KB total.
#define AF_BUF 4096
#define BF_BUF 4096
#define SMEM_BYTES ((2 * AF_BUF + 2 * BF_BUF) * 4)   // 65536

// h[r][M_PAD][128] : per-relation transformed features (pad rows never gathered)
__device__ float g_h[(size_t)3 * M_PAD * OUT_C];

static __device__ __forceinline__ uint32_t tf32_rna(float x) {
    uint32_t y;
    asm("cvt.rna.tf32.f32 %0, %1;" : "=r"(y) : "f"(x));
    return y;
}

// ---------------------------------------------------------------------------
// 1) GEMM: h_j = x @ W_j via mma.sync.m16n8k8.tf32 (HMMA).
//    Grid (782, 3). Fragment-ready smem: inner loop does 4 LDS.128 (A) +
//    4 LDS.64 (B) + 16 HMMA per k-step.
//
//    A_frag float index: ((ks*8 + tile16)*32 + g*4 + tg)*4 + (rhalf + 2*khalf)
//      tile16 = row/16, r16 = row%16, rhalf = r16/8, g = r16%8,
//      ks = klocal/8, tg = klocal%4, khalf = (klocal%8)/4
//    B_frag float index: ((ks*16 + ntile)*32 + g*4 + tg)*2 + khalf
//      ntile = n/8, g = n%8
// ---------------------------------------------------------------------------
__global__ __launch_bounds__(256, 2) void gemm_hmma_kernel(
        const float4* __restrict__ x4,
        const float* __restrict__ W0,
        const float* __restrict__ W1,
        const float* __restrict__ W2) {
    extern __shared__ float smem[];
    float* Af[2] = { smem,               smem + AF_BUF };
    float* Bf[2] = { smem + 2 * AF_BUF,  smem + 2 * AF_BUF + BF_BUF };

    int tid  = threadIdx.x;
    int lane = tid & 31;
    int wid  = tid >> 5;
    int wr   = wid >> 2;          // 0..1  (64-row slab)
    int wc   = wid & 3;           // 0..3  (32-col slab)
    int g    = lane >> 2;         // group id 0..7
    int tg   = lane & 3;          // thread-in-group 0..3

    int tile_row0 = blockIdx.x * M_TILE;
    const float* Wj = (blockIdx.y == 0) ? W0 : (blockIdx.y == 1 ? W1 : W2);
    float* hj = g_h + (size_t)blockIdx.y * M_PAD * OUT_C;

    // stage chunk c into buffer b, converting fp32->tf32 and scattering into
    // fragment order.
    auto stage = [&](int c, int b) {
        float* A = Af[b];
        float* B = Bf[b];
        #pragma unroll
        for (int i = tid; i < 1024; i += 256) {          // A: 128 rows x 8 f4
            int row = i >> 3, c4 = i & 7;                // klocal = c4*4 + j
            int srow = tile_row0 + row;
            if (srow >= N_NODES) srow = 0;               // pad rows: any value
            float4 v = __ldg(x4 + (size_t)srow * (IN_C / 4) + c * 8 + c4);
            int ks = c4 >> 1, kh = c4 & 1;
            int tile16 = row >> 4, r16 = row & 15;
            int rh = r16 >> 3, gg = r16 & 7;
            int base = ((ks * 8 + tile16) * 32 + gg * 4) * 4 + (rh + 2 * kh);
            A[base + 0 * 4] = __uint_as_float(tf32_rna(v.x));   // j = tg
            A[base + 1 * 4] = __uint_as_float(tf32_rna(v.y));
            A[base + 2 * 4] = __uint_as_float(tf32_rna(v.z));
            A[base + 3 * 4] = __uint_as_float(tf32_rna(v.w));
        }
        #pragma unroll
        for (int i = tid; i < 1024; i += 256) {          // B: 32 k-rows x 32 f4
            int k = i >> 5, n4 = i & 31;                 // n = n4*4 + j
            float4 v = __ldg(reinterpret_cast<const float4*>(
                             Wj + (size_t)(c * KCH + k) * OUT_C) + n4);
            int ks = k >> 3, ttg = k & 3, kh = (k & 7) >> 2;
            int ntile = n4 >> 1;
            int gbase = (n4 & 1) * 4;
            int base = ((ks * 16 + ntile) * 32 + ttg) * 2 + kh;
            B[base + (gbase + 0) * 8] = __uint_as_float(tf32_rna(v.x));
            B[base + (gbase + 1) * 8] = __uint_as_float(tf32_rna(v.y));
            B[base + (gbase + 2) * 8] = __uint_as_float(tf32_rna(v.z));
            B[base + (gbase + 3) * 8] = __uint_as_float(tf32_rna(v.w));
        }
    };

    float acc[4][4][4];
    #pragma unroll
    for (int mt = 0; mt < 4; mt++)
        #pragma unroll
        for (int nt = 0; nt < 4; nt++)
            #pragma unroll
            for (int r = 0; r < 4; r++) acc[mt][nt][r] = 0.f;

    stage(0, 0);
    __syncthreads();

    for (int c = 0; c < NCHUNK; c++) {
        int b = c & 1;
        if (c + 1 < NCHUNK) stage(c + 1, b ^ 1);

        const float4* A4 = reinterpret_cast<const float4*>(Af[b]);
        const float2* B2 = reinterpret_cast<const float2*>(Bf[b]);

        #pragma unroll
        for (int ks = 0; ks < KCH / 8; ks++) {
            float4 af[4];
            float2 bf[4];
            #pragma unroll
            for (int mt = 0; mt < 4; mt++)
                af[mt] = A4[(ks * 8 + wr * 4 + mt) * 32 + lane];
            #pragma unroll
            for (int nt = 0; nt < 4; nt++)
                bf[nt] = B2[(ks * 16 + wc * 4 + nt) * 32 + lane];

            #pragma unroll
            for (int mt = 0; mt < 4; mt++)
                #pragma unroll
                for (int nt = 0; nt < 4; nt++) {
                    asm volatile(
                        "mma.sync.aligned.m16n8k8.row.col.f32.tf32.tf32.f32 "
                        "{%0,%1,%2,%3}, {%4,%5,%6,%7}, {%8,%9}, {%0,%1,%2,%3};"
                        : "+f"(acc[mt][nt][0]), "+f"(acc[mt][nt][1]),
                          "+f"(acc[mt][nt][2]), "+f"(acc[mt][nt][3])
                        : "r"(__float_as_uint(af[mt].x)),
                          "r"(__float_as_uint(af[mt].y)),
                          "r"(__float_as_uint(af[mt].z)),
                          "r"(__float_as_uint(af[mt].w)),
                          "r"(__float_as_uint(bf[nt].x)),
                          "r"(__float_as_uint(bf[nt].y)));
                }
        }
        __syncthreads();
    }

    #pragma unroll
    for (int mt = 0; mt < 4; mt++) {
        int row = tile_row0 + wr * 64 + mt * 16 + g;
        #pragma unroll
        for (int nt = 0; nt < 4; nt++) {
            int col = wc * 32 + nt * 8 + 2 * tg;
            float2* p0 = reinterpret_cast<float2*>(hj + (size_t)row * OUT_C + col);
            float2* p1 = reinterpret_cast<float2*>(hj + (size_t)(row + 8) * OUT_C + col);
            *p0 = make_float2(acc[mt][nt][0], acc[mt][nt][1]);
            *p1 = make_float2(acc[mt][nt][2], acc[mt][nt][3]);
        }
    }
}

// ---------------------------------------------------------------------------
// 2) zero d_out
// ---------------------------------------------------------------------------
__global__ void zero_out_kernel(float4* __restrict__ out4) {
    size_t i = (size_t)blockIdx.x * blockDim.x + threadIdx.x;
    if (i < (size_t)N_NODES * OUT_C / 4)
        out4[i] = make_float4(0.f, 0.f, 0.f, 0.f);
}

// ---------------------------------------------------------------------------
// 3) scatter, 4 edges per warp: out[dst] += h_rel[src].
//    int4 index loads (warp-uniform LDG.128) + 4 independent gathers in
//    flight before the 4 REDs -> MLP 4.
// ---------------------------------------------------------------------------
__global__ void scatter_rel_kernel(float* __restrict__ out,
                                   int rel,
                                   const int* __restrict__ src,
                                   const int* __restrict__ dst) {
    unsigned gw   = (blockIdx.x * blockDim.x + threadIdx.x) >> 5;  // warp id
    int      lane = threadIdx.x & 31;
    if (gw >= (unsigned)(N_EDGES / 4)) return;

    int4 s4 = __ldg(reinterpret_cast<const int4*>(src) + gw);
    int4 d4 = __ldg(reinterpret_cast<const int4*>(dst) + gw);

    const float4* h4 = reinterpret_cast<const float4*>(
        g_h + (size_t)rel * M_PAD * OUT_C);

    float4 v0 = __ldg(h4 + (size_t)s4.x * (OUT_C / 4) + lane);
    float4 v1 = __ldg(h4 + (size_t)s4.y * (OUT_C / 4) + lane);
    float4 v2 = __ldg(h4 + (size_t)s4.z * (OUT_C / 4) + lane);
    float4 v3 = __ldg(h4 + (size_t)s4.w * (OUT_C / 4) + lane);

    float* p0 = out + (size_t)d4.x * OUT_C + lane * 4;
    float* p1 = out + (size_t)d4.y * OUT_C + lane * 4;
    float* p2 = out + (size_t)d4.z * OUT_C + lane * 4;
    float* p3 = out + (size_t)d4.w * OUT_C + lane * 4;
    asm volatile("red.global.add.v4.f32 [%0], {%1,%2,%3,%4};"
                 :: "l"(p0), "f"(v0.x), "f"(v0.y), "f"(v0.z), "f"(v0.w) : "memory");
    asm volatile("red.global.add.v4.f32 [%0], {%1,%2,%3,%4};"
                 :: "l"(p1), "f"(v1.x), "f"(v1.y), "f"(v1.z), "f"(v1.w) : "memory");
    asm volatile("red.global.add.v4.f32 [%0], {%1,%2,%3,%4};"
                 :: "l"(p2), "f"(v2.x), "f"(v2.y), "f"(v2.z), "f"(v2.w) : "memory");
    asm volatile("red.global.add.v4.f32 [%0], {%1,%2,%3,%4};"
                 :: "l"(p3), "f"(v3.x), "f"(v3.y), "f"(v3.z), "f"(v3.w) : "memory");
}

// ---------------------------------------------------------------------------
// 4) relu in place (2 float4 per thread)
// ---------------------------------------------------------------------------
__global__ void relu_kernel(float4* __restrict__ out4) {
    size_t base = (size_t)blockIdx.x * (blockDim.x * 2) + threadIdx.x;
    const size_t n4 = (size_t)N_NODES * OUT_C / 4;
    #pragma unroll
    for (int j = 0; j < 2; j++) {
        size_t i = base + (size_t)j * blockDim.x;
        if (i < n4) {
            float4 v = out4[i];
            v.x = fmaxf(v.x, 0.f); v.y = fmaxf(v.y, 0.f);
            v.z = fmaxf(v.z, 0.f); v.w = fmaxf(v.w, 0.f);
            out4[i] = v;
        }
    }
}

// ---------------------------------------------------------------------------
// launch
// ---------------------------------------------------------------------------
extern "C" void kernel_launch(void* const* d_in, const int* in_sizes, int n_in,
                              void* d_out, int out_size) {
    const float* x  = (const float*)d_in[0];
    const float* W0 = (const float*)d_in[1];
    const float* W1 = (const float*)d_in[2];
    const float* W2 = (const float*)d_in[3];
    const int* s0 = (const int*)d_in[4];
    const int* d0 = (const int*)d_in[5];
    const int* s1 = (const int*)d_in[6];
    const int* d1 = (const int*)d_in[7];
    const int* s2 = (const int*)d_in[8];
    const int* d2 = (const int*)d_in[9];
    float* out = (float*)d_out;

    // 1) zero the output accumulator
    {
        size_t n4 = (size_t)N_NODES * OUT_C / 4;
        zero_out_kernel<<<(int)((n4 + 255) / 256), 256>>>(
            reinterpret_cast<float4*>(out));
    }

    // 2) GEMM: h_r = x @ W_r (tensor cores, tf32)
    {
        static bool attr_set = false;   // idempotent attribute set
        if (!attr_set) {
            cudaFuncSetAttribute(gemm_hmma_kernel,
                                 cudaFuncAttributeMaxDynamicSharedMemorySize,
                                 SMEM_BYTES);
            attr_set = true;
        }
        dim3 grid(N_TILES, 3);
        gemm_hmma_kernel<<<grid, 256, SMEM_BYTES>>>(
            reinterpret_cast<const float4*>(x), W0, W1, W2);
    }

    // 3) scatter, one relation at a time, 4 edges per warp
    {
        long long warps = N_EDGES / 4;              // 150000
        int blocks = (int)((warps * 32 + 255) / 256);
        scatter_rel_kernel<<<blocks, 256>>>(out, 0, s0, d0);
        scatter_rel_kernel<<<blocks, 256>>>(out, 1, s1, d1);
        scatter_rel_kernel<<<blocks, 256>>>(out, 2, s2, d2);
    }

    // 4) relu in place
    {
        size_t n4 = (size_t)N_NODES * OUT_C / 4;
        int blocks = (int)((n4 + 1023) / 1024);
        relu_kernel<<<blocks, 512>>>(reinterpret_cast<float4*>(out));
    }
}

// round 7
// speedup vs baseline: 1.4464x; 1.4464x over previous
#include <cuda_runtime.h>
#include <cstdint>

#define N_NODES 100000
#define N_EDGES 600000
#define IN_C    128
#define OUT_C   128
#define M_TILE  128
#define N_TILES ((N_NODES + M_TILE - 1) / M_TILE)   // 782
#define M_PAD   (N_TILES * M_TILE)                  // 100096
#define KCH     32                                  // K per staged chunk
#define NCHUNK  (IN_C / KCH)                        // 4
#define AS_STRIDE 36                                // padded floats per A row
#define BS_STRIDE 136                               // padded floats per B row
#define AS_BUF   (M_TILE * AS_STRIDE)               // 4608 floats
#define BS_BUF   (KCH * BS_STRIDE)                  // 4352 floats
#define SMEM_FLOATS (2 * (AS_BUF + BS_BUF))
#define SMEM_BYTES  (SMEM_FLOATS * 4)               // 71680

// h[r][M_PAD][128] : per-relation transformed features (pad rows never gathered)
__device__ float g_h[(size_t)3 * M_PAD * OUT_C];

static __device__ __forceinline__ uint32_t tf32_rna(float x) {
    uint32_t y;
    asm("cvt.rna.tf32.f32 %0, %1;" : "=r"(y) : "f"(x));
    return y;
}

// ---------------------------------------------------------------------------
// 1) GEMM: h_j = x @ W_j via mma.sync.m16n8k8.tf32 (HMMA).  (R3 version)
// ---------------------------------------------------------------------------
__global__ __launch_bounds__(256, 2) void gemm_hmma_kernel(
        const float4* __restrict__ x4,
        const float* __restrict__ W0,
        const float* __restrict__ W1,
        const float* __restrict__ W2) {
    extern __shared__ float smem[];
    float* As[2] = { smem,                smem + AS_BUF };
    float* Bs[2] = { smem + 2 * AS_BUF,   smem + 2 * AS_BUF + BS_BUF };

    int tid  = threadIdx.x;
    int lane = tid & 31;
    int wid  = tid >> 5;
    int wr   = wid >> 2;          // 0..1  (64-row slab)
    int wc   = wid & 3;           // 0..3  (32-col slab)
    int g    = lane >> 2;         // group id 0..7
    int tg   = lane & 3;          // thread-in-group 0..3

    int tile_row0 = blockIdx.x * M_TILE;
    const float* Wj = (blockIdx.y == 0) ? W0 : (blockIdx.y == 1 ? W1 : W2);
    float* hj = g_h + (size_t)blockIdx.y * M_PAD * OUT_C;

    auto stage = [&](int c, int b) {
        float* A = As[b];
        float* B = Bs[b];
        #pragma unroll
        for (int i = tid; i < 1024; i += 256) {          // A: 128 rows x 8 f4
            int row = i >> 3, c4 = i & 7;
            int srow = tile_row0 + row;
            if (srow >= N_NODES) srow = 0;               // pad rows: any value
            float4 v = __ldg(x4 + (size_t)srow * (IN_C / 4) + c * 8 + c4);
            uint32_t* p = reinterpret_cast<uint32_t*>(A + row * AS_STRIDE + c4 * 4);
            p[0] = tf32_rna(v.x); p[1] = tf32_rna(v.y);
            p[2] = tf32_rna(v.z); p[3] = tf32_rna(v.w);
        }
        #pragma unroll
        for (int i = tid; i < 1024; i += 256) {          // B: 32 k-rows x 32 f4
            int k = i >> 5, n4 = i & 31;
            float4 v = __ldg(reinterpret_cast<const float4*>(
                             Wj + (size_t)(c * KCH + k) * OUT_C) + n4);
            uint32_t* p = reinterpret_cast<uint32_t*>(B + k * BS_STRIDE + n4 * 4);
            p[0] = tf32_rna(v.x); p[1] = tf32_rna(v.y);
            p[2] = tf32_rna(v.z); p[3] = tf32_rna(v.w);
        }
    };

    float acc[4][4][4];
    #pragma unroll
    for (int mt = 0; mt < 4; mt++)
        #pragma unroll
        for (int nt = 0; nt < 4; nt++)
            #pragma unroll
            for (int r = 0; r < 4; r++) acc[mt][nt][r] = 0.f;

    stage(0, 0);
    __syncthreads();

    for (int c = 0; c < NCHUNK; c++) {
        int b = c & 1;
        if (c + 1 < NCHUNK) stage(c + 1, b ^ 1);

        const uint32_t* A = reinterpret_cast<const uint32_t*>(As[b]);
        const uint32_t* B = reinterpret_cast<const uint32_t*>(Bs[b]);

        #pragma unroll
        for (int ks = 0; ks < KCH / 8; ks++) {
            int kk = ks * 8;
            uint32_t af[4][4], bf[4][2];
            #pragma unroll
            for (int mt = 0; mt < 4; mt++) {
                int m0 = wr * 64 + mt * 16 + g;
                af[mt][0] = A[(m0)     * AS_STRIDE + kk + tg];
                af[mt][1] = A[(m0 + 8) * AS_STRIDE + kk + tg];
                af[mt][2] = A[(m0)     * AS_STRIDE + kk + tg + 4];
                af[mt][3] = A[(m0 + 8) * AS_STRIDE + kk + tg + 4];
            }
            #pragma unroll
            for (int nt = 0; nt < 4; nt++) {
                int n0 = wc * 32 + nt * 8 + g;
                bf[nt][0] = B[(kk + tg)     * BS_STRIDE + n0];
                bf[nt][1] = B[(kk + tg + 4) * BS_STRIDE + n0];
            }
            #pragma unroll
            for (int mt = 0; mt < 4; mt++)
                #pragma unroll
                for (int nt = 0; nt < 4; nt++) {
                    asm volatile(
                        "mma.sync.aligned.m16n8k8.row.col.f32.tf32.tf32.f32 "
                        "{%0,%1,%2,%3}, {%4,%5,%6,%7}, {%8,%9}, {%0,%1,%2,%3};"
                        : "+f"(acc[mt][nt][0]), "+f"(acc[mt][nt][1]),
                          "+f"(acc[mt][nt][2]), "+f"(acc[mt][nt][3])
                        : "r"(af[mt][0]), "r"(af[mt][1]),
                          "r"(af[mt][2]), "r"(af[mt][3]),
                          "r"(bf[nt][0]), "r"(bf[nt][1]));
                }
        }
        __syncthreads();
    }

    #pragma unroll
    for (int mt = 0; mt < 4; mt++) {
        int row = tile_row0 + wr * 64 + mt * 16 + g;
        #pragma unroll
        for (int nt = 0; nt < 4; nt++) {
            int col = wc * 32 + nt * 8 + 2 * tg;
            float2* p0 = reinterpret_cast<float2*>(hj + (size_t)row * OUT_C + col);
            float2* p1 = reinterpret_cast<float2*>(hj + (size_t)(row + 8) * OUT_C + col);
            *p0 = make_float2(acc[mt][nt][0], acc[mt][nt][1]);
            *p1 = make_float2(acc[mt][nt][2], acc[mt][nt][3]);
        }
    }
}

// ---------------------------------------------------------------------------
// 2) zero d_out
// ---------------------------------------------------------------------------
__global__ void zero_out_kernel(float4* __restrict__ out4) {
    size_t i = (size_t)blockIdx.x * blockDim.x + threadIdx.x;
    if (i < (size_t)N_NODES * OUT_C / 4)
        out4[i] = make_float4(0.f, 0.f, 0.f, 0.f);
}

// ---------------------------------------------------------------------------
// 3) scatter, 8 edges per warp: out[dst] += h_rel[src].
//    Two int4 index loads per list, 8 independent gathers in flight, then
//    8 REDs -> MLP 8 on a latency-bound kernel.
// ---------------------------------------------------------------------------
__global__ void scatter_rel_kernel(float* __restrict__ out,
                                   int rel,
                                   const int* __restrict__ src,
                                   const int* __restrict__ dst) {
    unsigned gw   = (blockIdx.x * blockDim.x + threadIdx.x) >> 5;  // warp id
    int      lane = threadIdx.x & 31;
    if (gw >= (unsigned)(N_EDGES / 8)) return;

    const int4* s4p = reinterpret_cast<const int4*>(src) + gw * 2;
    const int4* d4p = reinterpret_cast<const int4*>(dst) + gw * 2;
    int4 sa = __ldg(s4p);
    int4 sb = __ldg(s4p + 1);
    int4 da = __ldg(d4p);
    int4 db = __ldg(d4p + 1);

    const float4* h4 = reinterpret_cast<const float4*>(
        g_h + (size_t)rel * M_PAD * OUT_C);

    int s[8] = { sa.x, sa.y, sa.z, sa.w, sb.x, sb.y, sb.z, sb.w };
    int d[8] = { da.x, da.y, da.z, da.w, db.x, db.y, db.z, db.w };

    float4 v[8];
    #pragma unroll
    for (int j = 0; j < 8; j++)
        v[j] = __ldg(h4 + (size_t)s[j] * (OUT_C / 4) + lane);

    #pragma unroll
    for (int j = 0; j < 8; j++) {
        float* p = out + (size_t)d[j] * OUT_C + lane * 4;
        asm volatile("red.global.add.v4.f32 [%0], {%1,%2,%3,%4};"
                     :: "l"(p), "f"(v[j].x), "f"(v[j].y), "f"(v[j].z), "f"(v[j].w)
                     : "memory");
    }
}

// ---------------------------------------------------------------------------
// 4) relu in place (2 float4 per thread)
// ---------------------------------------------------------------------------
__global__ void relu_kernel(float4* __restrict__ out4) {
    size_t base = (size_t)blockIdx.x * (blockDim.x * 2) + threadIdx.x;
    const size_t n4 = (size_t)N_NODES * OUT_C / 4;
    #pragma unroll
    for (int j = 0; j < 2; j++) {
        size_t i = base + (size_t)j * blockDim.x;
        if (i < n4) {
            float4 v = out4[i];
            v.x = fmaxf(v.x, 0.f); v.y = fmaxf(v.y, 0.f);
            v.z = fmaxf(v.z, 0.f); v.w = fmaxf(v.w, 0.f);
            out4[i] = v;
        }
    }
}

// ---------------------------------------------------------------------------
// launch
// ---------------------------------------------------------------------------
extern "C" void kernel_launch(void* const* d_in, const int* in_sizes, int n_in,
                              void* d_out, int out_size) {
    const float* x  = (const float*)d_in[0];
    const float* W0 = (const float*)d_in[1];
    const float* W1 = (const float*)d_in[2];
    const float* W2 = (const float*)d_in[3];
    const int* s0 = (const int*)d_in[4];
    const int* d0 = (const int*)d_in[5];
    const int* s1 = (const int*)d_in[6];
    const int* d1 = (const int*)d_in[7];
    const int* s2 = (const int*)d_in[8];
    const int* d2 = (const int*)d_in[9];
    float* out = (float*)d_out;

    // 1) zero the output accumulator
    {
        size_t n4 = (size_t)N_NODES * OUT_C / 4;
        zero_out_kernel<<<(int)((n4 + 255) / 256), 256>>>(
            reinterpret_cast<float4*>(out));
    }

    // 2) GEMM: h_r = x @ W_r (tensor cores, tf32)
    {
        static bool attr_set = false;   // idempotent attribute set
        if (!attr_set) {
            cudaFuncSetAttribute(gemm_hmma_kernel,
                                 cudaFuncAttributeMaxDynamicSharedMemorySize,
                                 SMEM_BYTES);
            attr_set = true;
        }
        dim3 grid(N_TILES, 3);
        gemm_hmma_kernel<<<grid, 256, SMEM_BYTES>>>(
            reinterpret_cast<const float4*>(x), W0, W1, W2);
    }

    // 3) scatter, one relation at a time, 8 edges per warp
    {
        long long warps = N_EDGES / 8;              // 75000
        int blocks = (int)((warps * 32 + 255) / 256);
        scatter_rel_kernel<<<blocks, 256>>>(out, 0, s0, d0);
        scatter_rel_kernel<<<blocks, 256>>>(out, 1, s1, d1);
        scatter_rel_kernel<<<blocks, 256>>>(out, 2, s2, d2);
    }

    // 4) relu in place
    {
        size_t n4 = (size_t)N_NODES * OUT_C / 4;
        int blocks = (int)((n4 + 1023) / 1024);
        relu_kernel<<<blocks, 512>>>(reinterpret_cast<float4*>(out));
    }
}

// round 8
// speedup vs baseline: 1.6932x; 1.1707x over previous
#include <cuda_runtime.h>
#include <cstdint>

#define N_NODES 100000
#define N_EDGES 600000
#define IN_C    128
#define OUT_C   128
#define M_TILE  128
#define N_TILES ((N_NODES + M_TILE - 1) / M_TILE)   // 782
#define M_PAD   (N_TILES * M_TILE)                  // 100096
#define KCH     32
#define NCHUNK  (IN_C / KCH)                        // 4
#define A_STRIDE 132                                 // full-K A tile row stride
#define BS_STRIDE 136
#define A_BUF   (M_TILE * A_STRIDE)                  // 16896 floats
#define B_BUF   (KCH * BS_STRIDE)                    // 4352 floats
#define SMEM_BYTES ((A_BUF + 2 * B_BUF) * 4)         // 102400

#define NB      (3 * N_NODES)                        // 300000 buckets
#define SCAN_BS 2048
#define SCAN_BLOCKS ((NB + SCAN_BS - 1) / SCAN_BS)   // 147

// h[r][M_PAD][128]
__device__ float g_h[(size_t)3 * M_PAD * OUT_C];
// CSR infrastructure
__device__ int g_cnt[NB];
__device__ int g_rowstart[NB + 1];
__device__ int g_cursor[NB];
__device__ int g_sorted[3 * N_EDGES];
__device__ int g_partial[SCAN_BLOCKS];

static __device__ __forceinline__ uint32_t tf32_rna(float x) {
    uint32_t y;
    asm("cvt.rna.tf32.f32 %0, %1;" : "=r"(y) : "f"(x));
    return y;
}

// ---------------------------------------------------------------------------
// 1) GEMM: h_j = x @ W_j. Full A tile staged ONCE, 3 relations looped inside.
// ---------------------------------------------------------------------------
__global__ __launch_bounds__(256, 2) void gemm_hmma_kernel(
        const float4* __restrict__ x4,
        const float* __restrict__ W0,
        const float* __restrict__ W1,
        const float* __restrict__ W2) {
    extern __shared__ float smem[];
    float* A  = smem;
    float* Bs[2] = { smem + A_BUF, smem + A_BUF + B_BUF };

    int tid  = threadIdx.x;
    int lane = tid & 31;
    int wid  = tid >> 5;
    int wr   = wid >> 2;
    int wc   = wid & 3;
    int g    = lane >> 2;
    int tg   = lane & 3;

    int tile_row0 = blockIdx.x * M_TILE;

    // stage full A tile: 128 rows x 128 K (tf32)
    #pragma unroll
    for (int i = tid; i < 4096; i += 256) {
        int row = i >> 5, c4 = i & 31;
        int srow = tile_row0 + row;
        if (srow >= N_NODES) srow = 0;               // pad rows: any value
        float4 v = __ldg(x4 + (size_t)srow * (IN_C / 4) + c4);
        uint32_t* p = reinterpret_cast<uint32_t*>(A + row * A_STRIDE + c4 * 4);
        p[0] = tf32_rna(v.x); p[1] = tf32_rna(v.y);
        p[2] = tf32_rna(v.z); p[3] = tf32_rna(v.w);
    }
    __syncthreads();

    const uint32_t* Au = reinterpret_cast<const uint32_t*>(A);

    for (int rel = 0; rel < 3; rel++) {
        const float* Wj = (rel == 0) ? W0 : (rel == 1 ? W1 : W2);
        float* hj = g_h + (size_t)rel * M_PAD * OUT_C;

        auto stageB = [&](int c, int b) {
            float* B = Bs[b];
            #pragma unroll
            for (int i = tid; i < 1024; i += 256) {
                int k = i >> 5, n4 = i & 31;
                float4 v = __ldg(reinterpret_cast<const float4*>(
                                 Wj + (size_t)(c * KCH + k) * OUT_C) + n4);
                uint32_t* p = reinterpret_cast<uint32_t*>(B + k * BS_STRIDE + n4 * 4);
                p[0] = tf32_rna(v.x); p[1] = tf32_rna(v.y);
                p[2] = tf32_rna(v.z); p[3] = tf32_rna(v.w);
            }
        };

        float acc[4][4][4];
        #pragma unroll
        for (int mt = 0; mt < 4; mt++)
            #pragma unroll
            for (int nt = 0; nt < 4; nt++)
                #pragma unroll
                for (int r = 0; r < 4; r++) acc[mt][nt][r] = 0.f;

        stageB(0, 0);
        __syncthreads();

        for (int c = 0; c < NCHUNK; c++) {
            int b = c & 1;
            if (c + 1 < NCHUNK) stageB(c + 1, b ^ 1);

            const uint32_t* B = reinterpret_cast<const uint32_t*>(Bs[b]);

            #pragma unroll
            for (int ks = 0; ks < KCH / 8; ks++) {
                int kk = c * KCH + ks * 8;               // absolute K for A
                int kb = ks * 8;                          // local K for B
                uint32_t af[4][4], bf[4][2];
                #pragma unroll
                for (int mt = 0; mt < 4; mt++) {
                    int m0 = wr * 64 + mt * 16 + g;
                    af[mt][0] = Au[(m0)     * A_STRIDE + kk + tg];
                    af[mt][1] = Au[(m0 + 8) * A_STRIDE + kk + tg];
                    af[mt][2] = Au[(m0)     * A_STRIDE + kk + tg + 4];
                    af[mt][3] = Au[(m0 + 8) * A_STRIDE + kk + tg + 4];
                }
                #pragma unroll
                for (int nt = 0; nt < 4; nt++) {
                    int n0 = wc * 32 + nt * 8 + g;
                    bf[nt][0] = B[(kb + tg)     * BS_STRIDE + n0];
                    bf[nt][1] = B[(kb + tg + 4) * BS_STRIDE + n0];
                }
                #pragma unroll
                for (int mt = 0; mt < 4; mt++)
                    #pragma unroll
                    for (int nt = 0; nt < 4; nt++) {
                        asm volatile(
                            "mma.sync.aligned.m16n8k8.row.col.f32.tf32.tf32.f32 "
                            "{%0,%1,%2,%3}, {%4,%5,%6,%7}, {%8,%9}, {%0,%1,%2,%3};"
                            : "+f"(acc[mt][nt][0]), "+f"(acc[mt][nt][1]),
                              "+f"(acc[mt][nt][2]), "+f"(acc[mt][nt][3])
                            : "r"(af[mt][0]), "r"(af[mt][1]),
                              "r"(af[mt][2]), "r"(af[mt][3]),
                              "r"(bf[nt][0]), "r"(bf[nt][1]));
                    }
            }
            __syncthreads();
        }

        #pragma unroll
        for (int mt = 0; mt < 4; mt++) {
            int row = tile_row0 + wr * 64 + mt * 16 + g;
            #pragma unroll
            for (int nt = 0; nt < 4; nt++) {
                int col = wc * 32 + nt * 8 + 2 * tg;
                float2* p0 = reinterpret_cast<float2*>(hj + (size_t)row * OUT_C + col);
                float2* p1 = reinterpret_cast<float2*>(hj + (size_t)(row + 8) * OUT_C + col);
                *p0 = make_float2(acc[mt][nt][0], acc[mt][nt][1]);
                *p1 = make_float2(acc[mt][nt][2], acc[mt][nt][3]);
            }
        }
    }
}

// ---------------------------------------------------------------------------
// CSR build: zero counts -> count -> scan (3 kernels) -> fill sorted src
// ---------------------------------------------------------------------------
__global__ void zero_cnt_kernel() {
    int i = blockIdx.x * blockDim.x + threadIdx.x;
    if (i < NB) g_cnt[i] = 0;
}

__global__ void count_kernel(const int* __restrict__ d0,
                             const int* __restrict__ d1,
                             const int* __restrict__ d2) {
    unsigned gid = blockIdx.x * blockDim.x + threadIdx.x;
    if (gid >= 3u * N_EDGES) return;
    int rel, e;
    const int* dp;
    if (gid < (unsigned)N_EDGES)          { rel = 0; e = gid;                dp = d0; }
    else if (gid < 2u * (unsigned)N_EDGES){ rel = 1; e = gid - N_EDGES;      dp = d1; }
    else                                  { rel = 2; e = gid - 2u * N_EDGES; dp = d2; }
    atomicAdd(&g_cnt[rel * N_NODES + __ldg(dp + e)], 1);
}

__global__ void scan_a_kernel() {      // per-block totals
    __shared__ int sb[256];
    int t = threadIdx.x;
    int base = blockIdx.x * SCAN_BS + t * 8;
    int sum = 0;
    #pragma unroll
    for (int j = 0; j < 8; j++) {
        int idx = base + j;
        if (idx < NB) sum += g_cnt[idx];
    }
    sb[t] = sum;
    __syncthreads();
    for (int off = 128; off > 0; off >>= 1) {
        if (t < off) sb[t] += sb[t + off];
        __syncthreads();
    }
    if (t == 0) g_partial[blockIdx.x] = sb[0];
}

__global__ void scan_b_kernel() {      // serial exclusive scan of partials
    if (threadIdx.x == 0 && blockIdx.x == 0) {
        int run = 0;
        for (int i = 0; i < SCAN_BLOCKS; i++) {
            int v = g_partial[i];
            g_partial[i] = run;
            run += v;
        }
        g_rowstart[NB] = run;          // = 3*N_EDGES
    }
}

__global__ void scan_c_kernel() {      // exclusive prefix + write rowstart/cursor
    __shared__ int sb[256];
    int t = threadIdx.x;
    int base = blockIdx.x * SCAN_BS + t * 8;
    int v[8];
    int tsum = 0;
    #pragma unroll
    for (int j = 0; j < 8; j++) {
        int idx = base + j;
        v[j] = (idx < NB) ? g_cnt[idx] : 0;
        tsum += v[j];
    }
    sb[t] = tsum;
    __syncthreads();
    // Hillis-Steele inclusive scan over 256 thread sums
    for (int off = 1; off < 256; off <<= 1) {
        int add = (t >= off) ? sb[t - off] : 0;
        __syncthreads();
        sb[t] += add;
        __syncthreads();
    }
    int run = g_partial[blockIdx.x] + sb[t] - tsum;   // exclusive for this thread
    #pragma unroll
    for (int j = 0; j < 8; j++) {
        int idx = base + j;
        if (idx < NB) {
            g_rowstart[idx] = run;
            g_cursor[idx] = run;
            run += v[j];
        }
    }
}

__global__ void fill_kernel(const int* __restrict__ s0, const int* __restrict__ d0,
                            const int* __restrict__ s1, const int* __restrict__ d1,
                            const int* __restrict__ s2, const int* __restrict__ d2) {
    unsigned gid = blockIdx.x * blockDim.x + threadIdx.x;
    if (gid >= 3u * N_EDGES) return;
    int rel, e;
    const int* sp;
    const int* dp;
    if (gid < (unsigned)N_EDGES)          { rel = 0; e = gid;                sp = s0; dp = d0; }
    else if (gid < 2u * (unsigned)N_EDGES){ rel = 1; e = gid - N_EDGES;      sp = s1; dp = d1; }
    else                                  { rel = 2; e = gid - 2u * N_EDGES; sp = s2; dp = d2; }
    int d = __ldg(dp + e);
    int pos = atomicAdd(&g_cursor[rel * N_NODES + d], 1);
    g_sorted[pos] = __ldg(sp + e);
}

// ---------------------------------------------------------------------------
// Gather: one warp per node; accumulate incoming h rows across 3 relations,
// relu, single store. No REDs, no zero pass, no relu pass.
// ---------------------------------------------------------------------------
__global__ void gather_kernel(float4* __restrict__ out4) {
    unsigned n    = (blockIdx.x * blockDim.x + threadIdx.x) >> 5;
    int      lane = threadIdx.x & 31;
    if (n >= (unsigned)N_NODES) return;

    const float4* h4 = reinterpret_cast<const float4*>(g_h);
    float4 acc = make_float4(0.f, 0.f, 0.f, 0.f);

    #pragma unroll
    for (int rel = 0; rel < 3; rel++) {
        int idx = rel * N_NODES + (int)n;
        int e   = __ldg(&g_rowstart[idx]);
        int end = __ldg(&g_rowstart[idx + 1]);
        size_t hbase = (size_t)rel * M_PAD * (OUT_C / 4);

        for (; e + 1 < end; e += 2) {
            int s0 = __ldg(&g_sorted[e]);
            int s1 = __ldg(&g_sorted[e + 1]);
            float4 v0 = __ldg(h4 + hbase + (size_t)s0 * (OUT_C / 4) + lane);
            float4 v1 = __ldg(h4 + hbase + (size_t)s1 * (OUT_C / 4) + lane);
            acc.x += v0.x + v1.x; acc.y += v0.y + v1.y;
            acc.z += v0.z + v1.z; acc.w += v0.w + v1.w;
        }
        if (e < end) {
            int s0 = __ldg(&g_sorted[e]);
            float4 v0 = __ldg(h4 + hbase + (size_t)s0 * (OUT_C / 4) + lane);
            acc.x += v0.x; acc.y += v0.y; acc.z += v0.z; acc.w += v0.w;
        }
    }

    acc.x = fmaxf(acc.x, 0.f); acc.y = fmaxf(acc.y, 0.f);
    acc.z = fmaxf(acc.z, 0.f); acc.w = fmaxf(acc.w, 0.f);
    out4[(size_t)n * (OUT_C / 4) + lane] = acc;
}

// ---------------------------------------------------------------------------
// launch
// ---------------------------------------------------------------------------
extern "C" void kernel_launch(void* const* d_in, const int* in_sizes, int n_in,
                              void* d_out, int out_size) {
    const float* x  = (const float*)d_in[0];
    const float* W0 = (const float*)d_in[1];
    const float* W1 = (const float*)d_in[2];
    const float* W2 = (const float*)d_in[3];
    const int* s0 = (const int*)d_in[4];
    const int* d0 = (const int*)d_in[5];
    const int* s1 = (const int*)d_in[6];
    const int* d1 = (const int*)d_in[7];
    const int* s2 = (const int*)d_in[8];
    const int* d2 = (const int*)d_in[9];
    float* out = (float*)d_out;

    // CSR build
    zero_cnt_kernel<<<(NB + 255) / 256, 256>>>();
    count_kernel<<<(3 * N_EDGES + 255) / 256, 256>>>(d0, d1, d2);
    scan_a_kernel<<<SCAN_BLOCKS, 256>>>();
    scan_b_kernel<<<1, 32>>>();
    scan_c_kernel<<<SCAN_BLOCKS, 256>>>();
    fill_kernel<<<(3 * N_EDGES + 255) / 256, 256>>>(s0, d0, s1, d1, s2, d2);

    // GEMM: h_r = x @ W_r (A staged once, 3 relations per CTA)
    {
        static bool attr_set = false;   // idempotent attribute set
        if (!attr_set) {
            cudaFuncSetAttribute(gemm_hmma_kernel,
                                 cudaFuncAttributeMaxDynamicSharedMemorySize,
                                 SMEM_BYTES);
            attr_set = true;
        }
        gemm_hmma_kernel<<<N_TILES, 256, SMEM_BYTES>>>(
            reinterpret_cast<const float4*>(x), W0, W1, W2);
    }

    // Gather + relu (one warp per node)
    {
        long long threads = (long long)N_NODES * 32;
        int blocks = (int)((threads + 255) / 256);
        gather_kernel<<<blocks, 256>>>(reinterpret_cast<float4*>(out));
    }
}